// round 4
// baseline (speedup 1.0000x reference)
#include <cuda_runtime.h>
#include <stdint.h>

// Output layout: fine_data [N*8, 64] f32, then fine_ijk [N*8, 3] written as f32
// (coords < 1024, exactly representable in f32).
//
// Fused kernel, 256 threads cover 32 coarse rows, 256-bit memory ops:
//   - data: thread t handles one 32B chunk of a coarse row (8 chunks/row),
//           loads it with ld.global.nc.v8 and stores it to the 8 fine rows
//           with st.global.v8 (STG.E.256).
//   - ijk:  threads 0..191 each emit one float4 of the ijk region
//           (32 rows * 24 floats = 192 float4 per block).

__device__ __forceinline__ void ldg256(const void* p, uint32_t r[8]) {
    asm volatile(
        "ld.global.nc.v8.b32 {%0,%1,%2,%3,%4,%5,%6,%7}, [%8];"
        : "=r"(r[0]), "=r"(r[1]), "=r"(r[2]), "=r"(r[3]),
          "=r"(r[4]), "=r"(r[5]), "=r"(r[6]), "=r"(r[7])
        : "l"(p));
}

__device__ __forceinline__ void stg256(void* p, const uint32_t r[8]) {
    asm volatile(
        "st.global.v8.b32 [%0], {%1,%2,%3,%4,%5,%6,%7,%8};"
        :: "l"(p),
           "r"(r[0]), "r"(r[1]), "r"(r[2]), "r"(r[3]),
           "r"(r[4]), "r"(r[5]), "r"(r[6]), "r"(r[7])
        : "memory");
}

__global__ void __launch_bounds__(256) upsample_fused_kernel(
    const float* __restrict__ src,      // coarse_data, N*64 floats
    const int* __restrict__ ijk,        // coarse_ijk, N*3 ints
    float* __restrict__ dst_data,       // fine_data, N*8*64 floats
    float4* __restrict__ dst_ijk,       // fine_ijk region as float4
    int n)
{
    const int t   = threadIdx.x;
    const int bid = blockIdx.x;

    // ---------- data load issued first (longest latency) ----------
    int idx = bid * 256 + t;                 // 32B-chunk index: chunk = idx&7, row = idx>>3
    bool do_data = (idx < n * 8);
    uint32_t v[8];
    if (do_data) ldg256(src + (long long)idx * 8, v);

    // ---------- ijk expansion ----------
    // Block covers coarse rows [bid*32, bid*32+32) -> 192 float4 of ijk output.
    if (t < 192) {
        long long q = (long long)bid * 192 + t;    // float4 index in ijk region
        if (q < (long long)n * 6) {
            long long e0 = q * 4;                  // first float element index
            float vals[4];
#pragma unroll
            for (int k = 0; k < 4; k++) {
                long long e = e0 + k;
                long long f = e / 3;               // fine voxel index
                int comp    = (int)(e - f * 3);    // 0,1,2
                long long cr = f >> 3;             // coarse row
                int sub      = (int)(f & 7);       // sub-voxel 0..7
                int c = __ldg(ijk + cr * 3 + comp);
                int off = (sub >> (2 - comp)) & 1; // meshgrid ij order
                vals[k] = (float)(2 * c + off);
            }
            dst_ijk[q] = make_float4(vals[0], vals[1], vals[2], vals[3]);
        }
    }

    // ---------- data replication (8 x 256-bit stores) ----------
    if (do_data) {
        int chunk = idx & 7;                       // 32B chunk within row
        long long cr = idx >> 3;                   // coarse row
        float* base = dst_data + cr * 512 + chunk * 8;  // 8 fine rows * 64 f32
#pragma unroll
        for (int j = 0; j < 8; j++) {
            stg256(base + j * 64, v);
        }
    }
}

extern "C" void kernel_launch(void* const* d_in, const int* in_sizes, int n_in,
                              void* d_out, int out_size) {
    const float* coarse_data = (const float*)d_in[0];
    const int*   coarse_ijk  = (const int*)d_in[1];
    float* out = (float*)d_out;

    int n = in_sizes[0] / 64;                       // coarse voxel count
    long long data_elems = (long long)n * 8 * 64;   // fine_data float count

    float*  dst_data = out;
    float4* dst_ijk  = (float4*)(out + data_elems);

    long long chunks = (long long)n * 8;            // 32B chunks total
    int blocks = (int)((chunks + 255) / 256);       // 32 coarse rows per block
    upsample_fused_kernel<<<blocks, 256>>>(coarse_data, coarse_ijk,
                                           dst_data, dst_ijk, n);
}